// round 16
// baseline (speedup 1.0000x reference)
#include <cuda_runtime.h>

// waspGridSpatialIntegral: input [B=64, 2, W=512, W=512] fp32.
//   out[:,0,:,:] = cumsum(in[:,0,:,:], axis=-1)  (contiguous width)
//   out[:,1,:,:] = cumsum(in[:,1,:,:], axis=-2)  (height, stride W)
//
// CONVERGED OPTIMUM (measured twice: 41.7-42.0 us kernel, 45.4-46.5 us dur,
// DRAM ~64%, 6.4 TB/s effective ~ 80% of spec). 13 measured variants
// established each element:
//   - __ldcs column loads: keeps the 32-load batch register-resident
//     (plain loads let ptxas interleave load+add: regs 40->32, +4 us)
//   - UNR=32 single batch: beat UNR=8 (+5 us), tied 16/16 pipeline,
//     beat 32/32 double buffer (regs 72, occupancy collapse, +7 us)
//   - block-per-row rows: beat warp-per-row (+2 us) and 2-row blocks (+1 us)
//   - 256 unsplit column blocks: beat both redundant-sum splits (+2-4 us;
//     the workload has no column tail to recover - row and column streams
//     drain together)
//   - columns at lowest blockIdx: long pole launches in wave 1
//   - column access is already streaming: 512 contiguous B per block-row
//
//   blocks [0, 256)        : column scans, ch 1
//   blocks [256, 256+32768): row scans, ch 0

#define W      512
#define WW     (512 * 512)
#define B      64
#define NROWS  (B * W)              // 32768 channel-0 rows
#define CTILES 4                    // 512 cols / 128 threads
#define NCOLB  (B * CTILES)         // 256 channel-1 blocks
#define UNR    32                   // column batch depth (MLP per thread)

__global__ __launch_bounds__(128) void wasp_integral_kernel(
    const float* __restrict__ in, float* __restrict__ out)
{
    const int bid = blockIdx.x;
    const int tid = threadIdx.x;

    if (bid < NCOLB) {
        // ------- channel 1: column scan (cumsum along y, stride W) -------
        const int b    = bid >> 2;
        const int tile = bid & 3;
        const int col  = tile * 128 + tid;
        const float* src = in  + (size_t)(b * 2 + 1) * WW + col;
        float*       dst = out + (size_t)(b * 2 + 1) * WW + col;

        float acc = 0.0f;
        for (int r = 0; r < W; r += UNR) {
            float v[UNR];
            #pragma unroll
            for (int i = 0; i < UNR; ++i)               // 32 loads in flight
                v[i] = __ldcs(src + (size_t)(r + i) * W);
            #pragma unroll
            for (int i = 0; i < UNR; ++i) {
                acc += v[i];
                __stcs(dst + (size_t)(r + i) * W, acc);
            }
        }
    } else {
        // ------- channel 0: row scan (cumsum along x, contiguous) -------
        const int rowid = bid - NCOLB;
        const int b     = rowid >> 9;
        const int y     = rowid & 511;
        const size_t base = (size_t)(b * 2) * WW + (size_t)y * W;

        const float4* src = reinterpret_cast<const float4*>(in + base);
        float4*       dst = reinterpret_cast<float4*>(out + base);

        float4 v = __ldcs(src + tid);
        v.y += v.x; v.z += v.y; v.w += v.z;   // local inclusive scan of 4

        const int lane = tid & 31;
        const int wid  = tid >> 5;

        float t = v.w;                         // warp scan of thread totals
        #pragma unroll
        for (int d = 1; d < 32; d <<= 1) {
            float n = __shfl_up_sync(0xFFFFFFFFu, t, d);
            if (lane >= d) t += n;
        }

        __shared__ float wsum[4];
        if (lane == 31) wsum[wid] = t;
        __syncthreads();

        float off = t - v.w;                   // intra-warp exclusive prefix
        #pragma unroll
        for (int w = 0; w < 3; ++w)
            if (wid > w) off += wsum[w];

        v.x += off; v.y += off; v.z += off; v.w += off;
        __stcs(dst + tid, v);
    }
}

extern "C" void kernel_launch(void* const* d_in, const int* in_sizes, int n_in,
                              void* d_out, int out_size)
{
    const float* in  = (const float*)d_in[0];
    float*       out = (float*)d_out;
    wasp_integral_kernel<<<NCOLB + NROWS, 128>>>(in, out);
}